// round 1
// baseline (speedup 1.0000x reference)
#include <cuda_runtime.h>

#define Sdim 512
#define SS (Sdim * Sdim)
#define Bn 8
#define KT 64
#define NTHREADS 256

// Pass-through copy for positions with r + c >= S (never touched by the
// diagonal linear). d_out is poisoned, so these must be written explicitly.
__global__ void copy_tail_kernel(const float* __restrict__ x,
                                 float* __restrict__ out) {
    int idx = blockIdx.x * blockDim.x + threadIdx.x;
    if (idx >= Bn * SS) return;
    int rc = idx & (SS - 1);
    int r = rc >> 9;
    int c = rc & (Sdim - 1);
    if (r + c >= Sdim) out[idx] = x[idx];
}

// One CTA per (diagonal i, 64-wide k tile).
// Gathers D[b][j] = x[b, j, i-j] (j <= i) to smem, then warp-per-k:
//   out[b, i-k, k] = sum_j W[i,k,j] * D[b][j] + bias[i,k]
__global__ void __launch_bounds__(NTHREADS)
diag_linear_kernel(const float* __restrict__ x,
                   const float* __restrict__ W,
                   const float* __restrict__ bias,
                   float* __restrict__ out) {
    // Reverse i so the heaviest diagonals are scheduled in the first wave.
    const int i = Sdim - 1 - (int)blockIdx.y;
    const int k0 = (int)blockIdx.x * KT;
    if (k0 > i) return;

    const int len = i + 1;
    const int kend = min(k0 + KT, len);

    __shared__ float Ds[Bn][Sdim];

    const int tid = threadIdx.x;

    // Cooperative gather of the anti-diagonal (scattered 4B reads; x fits in
    // L2 so repeats across k-tiles of the same diagonal are L2 hits).
    #pragma unroll
    for (int b = 0; b < Bn; b++) {
        const float* xb = x + (size_t)b * SS;
        for (int j = tid; j < len; j += NTHREADS) {
            Ds[b][j] = __ldg(xb + (size_t)j * Sdim + (i - j));
        }
    }
    __syncthreads();

    const int warp = tid >> 5;
    const int lane = tid & 31;

    for (int k = k0 + warp; k < kend; k += (NTHREADS / 32)) {
        const float* wrow = W + ((size_t)i * Sdim + k) * Sdim;
        const float4* w4p = (const float4*)wrow;

        float acc[Bn];
        #pragma unroll
        for (int b = 0; b < Bn; b++) acc[b] = 0.0f;

        const int len4 = len >> 2;
        for (int t = lane; t < len4; t += 32) {
            float4 w4 = w4p[t];
            int j = t << 2;
            #pragma unroll
            for (int b = 0; b < Bn; b++) {
                acc[b] += w4.x * Ds[b][j]
                        + w4.y * Ds[b][j + 1]
                        + w4.z * Ds[b][j + 2]
                        + w4.w * Ds[b][j + 3];
            }
        }
        // Remainder (len % 4)
        for (int j = (len4 << 2) + lane; j < len; j += 32) {
            float w = wrow[j];
            #pragma unroll
            for (int b = 0; b < Bn; b++) acc[b] += w * Ds[b][j];
        }

        // Warp butterfly reduction of 8 accumulators.
        #pragma unroll
        for (int off = 16; off > 0; off >>= 1) {
            #pragma unroll
            for (int b = 0; b < Bn; b++) {
                acc[b] += __shfl_xor_sync(0xffffffffu, acc[b], off);
            }
        }

        if (lane == 0) {
            const float bb = __ldg(bias + (size_t)i * Sdim + k);
            const int r = i - k;
            #pragma unroll
            for (int b = 0; b < Bn; b++) {
                out[(size_t)b * SS + (size_t)r * Sdim + k] = acc[b] + bb;
            }
        }
    }
}

extern "C" void kernel_launch(void* const* d_in, const int* in_sizes, int n_in,
                              void* d_out, int out_size) {
    const float* x = (const float*)d_in[0];
    const float* W = (const float*)d_in[1];
    const float* b = (const float*)d_in[2];
    float* out = (float*)d_out;

    // Fill the pass-through (r + c >= S) region.
    copy_tail_kernel<<<(Bn * SS + NTHREADS - 1) / NTHREADS, NTHREADS>>>(x, out);

    // Per-diagonal batched linear.
    dim3 grid(Sdim / KT, Sdim);
    diag_linear_kernel<<<grid, NTHREADS>>>(x, W, b, out);
}

// round 2
// speedup vs baseline: 1.2208x; 1.2208x over previous
#include <cuda_runtime.h>

#define Sdim 512
#define SS (Sdim * Sdim)
#define Bn 8
#define KT 64
#define NTHREADS 256

// Pass-through copy for positions with r + c >= S.
__global__ void copy_tail_kernel(const float* __restrict__ x,
                                 float* __restrict__ out) {
    int idx = blockIdx.x * blockDim.x + threadIdx.x;
    if (idx >= Bn * SS) return;
    int rc = idx & (SS - 1);
    int r = rc >> 9;
    int c = rc & (Sdim - 1);
    if (r + c >= Sdim) out[idx] = x[idx];
}

// One CTA per (diagonal i, 64-wide k tile).
//   out[b, i-k, k] = sum_j W[i,k,j] * D[b][j] + bias[i,k],  D[b][j]=x[b,j,i-j]
__global__ void __launch_bounds__(NTHREADS)
diag_linear_kernel(const float* __restrict__ x,
                   const float* __restrict__ W,
                   const float* __restrict__ bias,
                   float* __restrict__ out) {
    const int i = Sdim - 1 - (int)blockIdx.y;   // heavy diagonals first
    const int k0 = (int)blockIdx.x * KT;
    if (k0 > i) return;

    const int len = i + 1;
    const int kend = min(k0 + KT, len);

    __shared__ float Ds[Bn][Sdim];

    const int tid = threadIdx.x;

    // Gather anti-diagonal into smem (scattered 4B reads, mostly L2 hits).
    #pragma unroll
    for (int b = 0; b < Bn; b++) {
        const float* xb = x + (size_t)b * SS;
        for (int j = tid; j < len; j += NTHREADS) {
            Ds[b][j] = __ldg(xb + (size_t)j * Sdim + (i - j));
        }
    }
    __syncthreads();

    const int warp = tid >> 5;
    const int lane = tid & 31;
    const float* Wbase = W + (size_t)i * Sdim * Sdim;

    if (k0 + KT <= len) {
        // ---- Full-tile fast path: each warp processes 4 k-rows at once,
        //      reusing each smem float4 across all 4 (4x less LDS traffic).
        #pragma unroll
        for (int p = 0; p < 2; p++) {
            const int kk = k0 + p * 32 + warp * 4;
            const float4* wr0 = (const float4*)(Wbase + (size_t)(kk + 0) * Sdim);
            const float4* wr1 = (const float4*)(Wbase + (size_t)(kk + 1) * Sdim);
            const float4* wr2 = (const float4*)(Wbase + (size_t)(kk + 2) * Sdim);
            const float4* wr3 = (const float4*)(Wbase + (size_t)(kk + 3) * Sdim);

            float acc[4][Bn];
            #pragma unroll
            for (int u = 0; u < 4; u++)
                #pragma unroll
                for (int b = 0; b < Bn; b++) acc[u][b] = 0.0f;

            const int len4 = len >> 2;
            for (int t = lane; t < len4; t += 32) {
                float4 w0 = __ldcs(wr0 + t);
                float4 w1 = __ldcs(wr1 + t);
                float4 w2 = __ldcs(wr2 + t);
                float4 w3 = __ldcs(wr3 + t);
                #pragma unroll
                for (int b = 0; b < Bn; b++) {
                    float4 d = ((const float4*)Ds[b])[t];
                    acc[0][b] += w0.x * d.x + w0.y * d.y + w0.z * d.z + w0.w * d.w;
                    acc[1][b] += w1.x * d.x + w1.y * d.y + w1.z * d.z + w1.w * d.w;
                    acc[2][b] += w2.x * d.x + w2.y * d.y + w2.z * d.z + w2.w * d.w;
                    acc[3][b] += w3.x * d.x + w3.y * d.y + w3.z * d.z + w3.w * d.w;
                }
            }
            // Remainder (len % 4 <= 3): one element per low lane.
            const int rem = len & 3;
            if (lane < rem) {
                const int j = (len4 << 2) + lane;
                float w0s = Wbase[(size_t)(kk + 0) * Sdim + j];
                float w1s = Wbase[(size_t)(kk + 1) * Sdim + j];
                float w2s = Wbase[(size_t)(kk + 2) * Sdim + j];
                float w3s = Wbase[(size_t)(kk + 3) * Sdim + j];
                #pragma unroll
                for (int b = 0; b < Bn; b++) {
                    float dv = Ds[b][j];
                    acc[0][b] += w0s * dv;
                    acc[1][b] += w1s * dv;
                    acc[2][b] += w2s * dv;
                    acc[3][b] += w3s * dv;
                }
            }

            // Butterfly reduce all 32 accumulators across the warp.
            #pragma unroll
            for (int off = 16; off > 0; off >>= 1) {
                #pragma unroll
                for (int u = 0; u < 4; u++)
                    #pragma unroll
                    for (int b = 0; b < Bn; b++)
                        acc[u][b] += __shfl_xor_sync(0xffffffffu, acc[u][b], off);
            }

            if (lane == 0) {
                #pragma unroll
                for (int u = 0; u < 4; u++) {
                    const int k = kk + u;
                    const float bb = __ldg(bias + (size_t)i * Sdim + k);
                    const int r = i - k;
                    #pragma unroll
                    for (int b = 0; b < Bn; b++) {
                        out[(size_t)b * SS + (size_t)r * Sdim + k] = acc[u][b] + bb;
                    }
                }
            }
        }
    } else {
        // ---- Boundary path (partial k tile): warp-per-k, stride 8.
        for (int k = k0 + warp; k < kend; k += (NTHREADS / 32)) {
            const float* wrow = Wbase + (size_t)k * Sdim;
            const float4* w4p = (const float4*)wrow;

            float acc[Bn];
            #pragma unroll
            for (int b = 0; b < Bn; b++) acc[b] = 0.0f;

            const int len4 = len >> 2;
            for (int t = lane; t < len4; t += 32) {
                float4 w4 = __ldcs(w4p + t);
                #pragma unroll
                for (int b = 0; b < Bn; b++) {
                    float4 d = ((const float4*)Ds[b])[t];
                    acc[b] += w4.x * d.x + w4.y * d.y + w4.z * d.z + w4.w * d.w;
                }
            }
            for (int j = (len4 << 2) + lane; j < len; j += 32) {
                float w = wrow[j];
                #pragma unroll
                for (int b = 0; b < Bn; b++) acc[b] += w * Ds[b][j];
            }

            #pragma unroll
            for (int off = 16; off > 0; off >>= 1) {
                #pragma unroll
                for (int b = 0; b < Bn; b++)
                    acc[b] += __shfl_xor_sync(0xffffffffu, acc[b], off);
            }

            if (lane == 0) {
                const float bb = __ldg(bias + (size_t)i * Sdim + k);
                const int r = i - k;
                #pragma unroll
                for (int b = 0; b < Bn; b++) {
                    out[(size_t)b * SS + (size_t)r * Sdim + k] = acc[b] + bb;
                }
            }
        }
    }
}

extern "C" void kernel_launch(void* const* d_in, const int* in_sizes, int n_in,
                              void* d_out, int out_size) {
    const float* x = (const float*)d_in[0];
    const float* W = (const float*)d_in[1];
    const float* b = (const float*)d_in[2];
    float* out = (float*)d_out;

    copy_tail_kernel<<<(Bn * SS + NTHREADS - 1) / NTHREADS, NTHREADS>>>(x, out);

    dim3 grid(Sdim / KT, Sdim);
    diag_linear_kernel<<<grid, NTHREADS>>>(x, W, b, out);
}